// round 12
// baseline (speedup 1.0000x reference)
#include <cuda_runtime.h>
#include <cstdint>

// ---------------- problem constants ----------------
#define NPTS   1000000
#define FX     512
#define FY     512
#define FZ     64
#define FIN    64
#define FH     32
#define SCORE_T 0.1f
#define CENT_T  0.2f
#define MAXP    128
#define CCAP    2048
#define BIN1_BASE 0x3E4Cu      // float_bits(0.2) >> 16 ; peak scores in (0.2, 1.0)
#define NBIN1  512

// padded grid: [2][514][514][66], pad cells always 0
#define PX 514
#define PY 514
#define PZ 66
#define PCELLS (2*PX*PY*PZ)
#define DXS (PY*PZ)            // 33924
#define DYS (PZ)               // 66

// ---------------- device scratch (zero-init at module load) ----------------
__device__ __align__(16) unsigned int g_grid[PCELLS];
__device__ int                g_cell[NPTS];     // packed coords (b<<24|x<<15|y<<6|z)
__device__ int                g_touch[NPTS];    // padded cells with s>0.1 (to reset)
__device__ unsigned long long g_cand[NPTS];     // s>0.2 candidates: (sb<<32)|~idx
__device__ int                g_ccellp[NPTS];   // padded cell per candidate
__device__ unsigned long long g_keys[NPTS];     // peaks
__device__ unsigned long long g_ckeys[CCAP];    // threshold survivors
__device__ __align__(16) int  g_hist1[NBIN1];
__device__ int g_touch_count, g_cand_count, g_peak_count, g_ccount;
__device__ unsigned int g_thresh;

// ---------------- f32x2 helpers ----------------
__device__ __forceinline__ unsigned long long pk2(float x) {
    unsigned long long r; unsigned xi = __float_as_uint(x);
    asm("mov.b64 %0, {%1, %1};" : "=l"(r) : "r"(xi));
    return r;
}
__device__ __forceinline__ void fma2(unsigned long long& d, unsigned long long a, unsigned long long b) {
    asm("fma.rn.f32x2 %0, %1, %2, %0;" : "+l"(d) : "l"(a), "l"(b));
}
__device__ __forceinline__ float2 up2(unsigned long long v) {
    unsigned a, b;
    asm("mov.b64 {%0, %1}, %2;" : "=r"(a), "=r"(b) : "l"(v));
    return make_float2(__uint_as_float(a), __uint_as_float(b));
}

// ---------------- K A1: cleanup grid via prev replay's touch list ----------------
__global__ void __launch_bounds__(256) k_clean_grid()
{
    int tn  = g_touch_count;
    int gsz = gridDim.x * blockDim.x;
    for (int i = blockIdx.x * blockDim.x + threadIdx.x; i < tn; i += gsz)
        g_grid[g_touch[i]] = 0u;
}

// ---------------- K A2: clear hist + reset counters (after clean_grid) ----------
__global__ void __launch_bounds__(NBIN1) k_prep()
{
    g_hist1[threadIdx.x] = 0;
    if (threadIdx.x == 0) {
        g_touch_count = 0; g_cand_count = 0; g_peak_count = 0; g_ccount = 0;
    }
}

// ---------------- K1 (4th launch -> ncu target): register-blocked GEMM MLP --------
// Block: 256 points x 32 hidden. Thread (tid = m_grp*8 + n_grp):
//   8 points x 4 cols, acc as 16 x f32x2; inner loop split into 2x4 points to
//   cap live registers (target: 3 blocks/SM).
__global__ void __launch_bounds__(256, 3) k_mlp(
    const float* __restrict__ feats,
    const int*   __restrict__ cb, const int* __restrict__ cx,
    const int*   __restrict__ cy, const int* __restrict__ cz,
    const int*   __restrict__ mask,
    const float* __restrict__ W1, const float* __restrict__ b1,
    const float* __restrict__ W2, const float* __restrict__ b2,
    float* __restrict__ out_score)
{
    __shared__ __align__(16) float4 sF4[256 * 8];   // 32 KB: one 32-feature chunk
    __shared__ __align__(16) float  sW1s[FIN * FH]; // 8 KB  [k][n]
    __shared__ __align__(16) float  sb1s[FH];
    __shared__ __align__(16) float  sW2s[FH];
    __shared__ float sb2s;

    int t = threadIdx.x;
    for (int i = t; i < FIN * FH; i += 256) sW1s[i] = W1[i];
    if (t < FH) { sb1s[t] = b1[t]; sW2s[t] = W2[t]; }
    if (t == 0) sb2s = b2[0];

    int blockBase = blockIdx.x * 256;
    int m_grp = t >> 3;            // 0..31
    int n_grp = t & 7;             // 0..7
    int sw    = 2 * (m_grp & 3);   // XOR swizzle for this thread's point rows

    const float4* F4 = reinterpret_cast<const float4*>(feats);

    // ---- stage chunk 0 (features 0..31) ----
    #pragma unroll
    for (int u = 0; u < 8; u++) {
        int lin = u * 256 + t;
        int p   = lin >> 3;
        int f4  = lin & 7;
        int gp  = blockBase + p; if (gp >= NPTS) gp = NPTS - 1;
        sF4[p * 8 + (f4 ^ (2 * ((p >> 3) & 3)))] = F4[(size_t)gp * 16 + f4];
    }
    __syncthreads();

    unsigned long long acc[16];
    {
        ulonglong2 binit = *reinterpret_cast<const ulonglong2*>(&sb1s[n_grp * 4]);
        #pragma unroll
        for (int pp = 0; pp < 8; pp++) { acc[2 * pp] = binit.x; acc[2 * pp + 1] = binit.y; }
    }

    // ---- consume chunk 0 (two 4-point halves to limit live registers) ----
    #pragma unroll
    for (int k4 = 0; k4 < 8; k4++) {
        ulonglong2 w0 = *reinterpret_cast<const ulonglong2*>(&sW1s[(k4 * 4 + 0) * FH + n_grp * 4]);
        ulonglong2 w1 = *reinterpret_cast<const ulonglong2*>(&sW1s[(k4 * 4 + 1) * FH + n_grp * 4]);
        ulonglong2 w2 = *reinterpret_cast<const ulonglong2*>(&sW1s[(k4 * 4 + 2) * FH + n_grp * 4]);
        ulonglong2 w3 = *reinterpret_cast<const ulonglong2*>(&sW1s[(k4 * 4 + 3) * FH + n_grp * 4]);
        #pragma unroll
        for (int h = 0; h < 2; h++) {
            #pragma unroll
            for (int pq = 0; pq < 4; pq++) {
                int pp = h * 4 + pq;
                float4 fv = sF4[(m_grp * 8 + pp) * 8 + (k4 ^ sw)];
                unsigned long long fp;
                fp = pk2(fv.x); fma2(acc[2*pp], fp, w0.x); fma2(acc[2*pp+1], fp, w0.y);
                fp = pk2(fv.y); fma2(acc[2*pp], fp, w1.x); fma2(acc[2*pp+1], fp, w1.y);
                fp = pk2(fv.z); fma2(acc[2*pp], fp, w2.x); fma2(acc[2*pp+1], fp, w2.y);
                fp = pk2(fv.w); fma2(acc[2*pp], fp, w3.x); fma2(acc[2*pp+1], fp, w3.y);
            }
        }
    }
    __syncthreads();

    // ---- stage chunk 1 (features 32..63) ----
    #pragma unroll
    for (int u = 0; u < 8; u++) {
        int lin = u * 256 + t;
        int p   = lin >> 3;
        int f4  = lin & 7;
        int gp  = blockBase + p; if (gp >= NPTS) gp = NPTS - 1;
        sF4[p * 8 + (f4 ^ (2 * ((p >> 3) & 3)))] = F4[(size_t)gp * 16 + 8 + f4];
    }
    __syncthreads();

    // ---- consume chunk 1 ----
    #pragma unroll
    for (int k4 = 0; k4 < 8; k4++) {
        ulonglong2 w0 = *reinterpret_cast<const ulonglong2*>(&sW1s[(32 + k4 * 4 + 0) * FH + n_grp * 4]);
        ulonglong2 w1 = *reinterpret_cast<const ulonglong2*>(&sW1s[(32 + k4 * 4 + 1) * FH + n_grp * 4]);
        ulonglong2 w2 = *reinterpret_cast<const ulonglong2*>(&sW1s[(32 + k4 * 4 + 2) * FH + n_grp * 4]);
        ulonglong2 w3 = *reinterpret_cast<const ulonglong2*>(&sW1s[(32 + k4 * 4 + 3) * FH + n_grp * 4]);
        #pragma unroll
        for (int h = 0; h < 2; h++) {
            #pragma unroll
            for (int pq = 0; pq < 4; pq++) {
                int pp = h * 4 + pq;
                float4 fv = sF4[(m_grp * 8 + pp) * 8 + (k4 ^ sw)];
                unsigned long long fp;
                fp = pk2(fv.x); fma2(acc[2*pp], fp, w0.x); fma2(acc[2*pp+1], fp, w0.y);
                fp = pk2(fv.y); fma2(acc[2*pp], fp, w1.x); fma2(acc[2*pp+1], fp, w1.y);
                fp = pk2(fv.z); fma2(acc[2*pp], fp, w2.x); fma2(acc[2*pp+1], fp, w2.y);
                fp = pk2(fv.w); fma2(acc[2*pp], fp, w3.x); fma2(acc[2*pp+1], fp, w3.y);
            }
        }
    }

    // ---- second layer: per-thread partial over its 4 cols, butterfly over n_grp ----
    float4 w2v = *reinterpret_cast<const float4*>(&sW2s[n_grp * 4]);
    float part[8];
    #pragma unroll
    for (int pp = 0; pp < 8; pp++) {
        float2 a0 = up2(acc[2 * pp]);
        float2 a1 = up2(acc[2 * pp + 1]);
        float p0 = fmaxf(a0.x, 0.0f) * w2v.x;
        p0 = fmaf(fmaxf(a0.y, 0.0f), w2v.y, p0);
        p0 = fmaf(fmaxf(a1.x, 0.0f), w2v.z, p0);
        p0 = fmaf(fmaxf(a1.y, 0.0f), w2v.w, p0);
        part[pp] = p0;
    }
    #pragma unroll
    for (int off = 1; off < 8; off <<= 1) {
        #pragma unroll
        for (int pp = 0; pp < 8; pp++)
            part[pp] += __shfl_xor_sync(0xFFFFFFFFu, part[pp], off);
    }
    float z = part[n_grp] + sb2s;   // lane's point = blockBase + m_grp*8 + n_grp = blockBase + t

    // ---- epilogue ----
    int i = blockBase + t;
    bool valid = (i < NPTS);
    float s = 0.0f;
    int cellp = 0;
    unsigned sb = 0u;
    if (valid) {
        s = 1.0f / (1.0f + expf(-z));
        if (mask[i] == 0) s = 0.0f;
        out_score[i] = s;
        int b = cb[i], x = cx[i], y = cy[i], zc = cz[i];
        g_cell[i] = (b << 24) | (x << 15) | (y << 6) | zc;
        cellp = ((b * PX + x + 1) * PY + y + 1) * PZ + (zc + 1);
        sb = __float_as_uint(s);
    }
    int lane = t & 31;

    bool dep = valid && (s > SCORE_T);
    if (dep) atomicMax(&g_grid[cellp], sb);
    unsigned m = __ballot_sync(0xFFFFFFFFu, dep);
    int base = 0;
    if (lane == 0 && m) base = atomicAdd(&g_touch_count, __popc(m));
    base = __shfl_sync(0xFFFFFFFFu, base, 0);
    if (dep) g_touch[base + __popc(m & ((1u << lane) - 1u))] = cellp;

    bool cnd = valid && (s > CENT_T);
    unsigned m2 = __ballot_sync(0xFFFFFFFFu, cnd);
    int base2 = 0;
    if (lane == 0 && m2) base2 = atomicAdd(&g_cand_count, __popc(m2));
    base2 = __shfl_sync(0xFFFFFFFFu, base2, 0);
    if (cnd) {
        int pos = base2 + __popc(m2 & ((1u << lane) - 1u));
        g_cand[pos]   = ((unsigned long long)sb << 32) | (unsigned)(~(unsigned)i);
        g_ccellp[pos] = cellp;
    }
}

// ---------------- K2: peak detect (3-scalar-load rows; proven fastest) ----------
__global__ void __launch_bounds__(256) k_peak()
{
    int n   = g_cand_count;
    int gsz = gridDim.x * blockDim.x;
    int idx = blockIdx.x * blockDim.x + threadIdx.x;
    int iters = (n + gsz - 1) / gsz;
    int lane = threadIdx.x & 31;

    for (int it = 0; it < iters; it++, idx += gsz) {
        bool valid = (idx < n);
        unsigned long long key = 0ULL;
        unsigned sb = 0u, hmax = 0u;
        if (valid) {
            key = g_cand[idx];
            sb  = (unsigned)(key >> 32);
            int cp = g_ccellp[idx];
            #pragma unroll
            for (int dx = -1; dx <= 1; dx++) {
                #pragma unroll
                for (int dy = -1; dy <= 1; dy++) {
                    const unsigned* p = &g_grid[cp + dx * DXS + dy * DYS];
                    unsigned a = p[-1], b = p[0], c = p[1];
                    unsigned mx = a > b ? a : b;
                    mx = c > mx ? c : mx;
                    hmax = mx > hmax ? mx : hmax;
                }
            }
        }
        bool isPeak = valid && (hmax == sb);
        unsigned m = __ballot_sync(0xFFFFFFFFu, isPeak);
        int base = 0;
        if (lane == 0 && m) base = atomicAdd(&g_peak_count, __popc(m));
        base = __shfl_sync(0xFFFFFFFFu, base, 0);
        if (isPeak) {
            g_keys[base + __popc(m & ((1u << lane) - 1u))] = key;
            atomicAdd(&g_hist1[(sb >> 16) - BIN1_BASE], 1);
        }
    }
}

// ---------------- K3: single-level threshold (1 block, 512 thr) ----------------
__global__ void __launch_bounds__(NBIN1) k_thresh()
{
    __shared__ int csum[NBIN1];
    int t = threadIdx.x;
    int h = g_hist1[t];
    csum[t] = h;
    __syncthreads();
    for (int off = 1; off < NBIN1; off <<= 1) {
        int v = (t >= off) ? csum[t - off] : 0;
        __syncthreads();
        csum[t] += v;
        __syncthreads();
    }
    int total = csum[NBIN1 - 1];
    if (total < MAXP) {
        if (t == 0) g_thresh = 0u;      // take all peaks
        return;
    }
    int above = total - csum[t];        // strictly above bin t
    if (above < MAXP && above + h >= MAXP)
        g_thresh = ((unsigned)(t + BIN1_BASE)) << 16;
}

// ---------------- K4: compact survivors (grid-wide) ----------------
__global__ void __launch_bounds__(256) k_compact()
{
    int n = g_peak_count;
    unsigned th = g_thresh;
    int gsz = gridDim.x * blockDim.x;
    int idx = blockIdx.x * blockDim.x + threadIdx.x;
    int iters = (n + gsz - 1) / gsz;
    int lane = threadIdx.x & 31;
    for (int it = 0; it < iters; it++, idx += gsz) {
        bool take = false;
        unsigned long long key = 0ULL;
        if (idx < n) {
            key = g_keys[idx];
            take = ((unsigned)(key >> 32) >= th);
        }
        unsigned m = __ballot_sync(0xFFFFFFFFu, take);
        int base = 0;
        if (lane == 0 && m) base = atomicAdd(&g_ccount, __popc(m));
        base = __shfl_sync(0xFFFFFFFFu, base, 0);
        if (take) {
            int pos = base + __popc(m & ((1u << lane) - 1u));
            if (pos < CCAP) g_ckeys[pos] = key;
        }
    }
}

// ---------------- K5: sort 2048 + emit outputs (1 block, 1024 thr) ----------------
__global__ void __launch_bounds__(1024) k_sortout(float* __restrict__ out)
{
    __shared__ unsigned long long sk[CCAP];     // 16 KB
    __shared__ int fill[MAXP];
    __shared__ int sValid;
    int t = threadIdx.x;
    int M = g_ccount; if (M > CCAP) M = CCAP;
    sk[t]        = (t        < M) ? g_ckeys[t]        : 0ULL;
    sk[t + 1024] = (t + 1024 < M) ? g_ckeys[t + 1024] : 0ULL;
    __syncthreads();

    // bitonic sort, descending (2048 elems, 2/thread)
    for (int kk = 2; kk <= CCAP; kk <<= 1) {
        for (int j = kk >> 1; j > 0; j >>= 1) {
            #pragma unroll
            for (int half = 0; half < 2; half++) {
                int i = t + half * 1024;
                int ixj = i ^ j;
                if (ixj > i) {
                    unsigned long long a = sk[i], b = sk[ixj];
                    bool desc = ((i & kk) == 0);
                    if (desc ? (a < b) : (a > b)) { sk[i] = b; sk[ixj] = a; }
                }
            }
            __syncthreads();
        }
    }

    if (t == 0) {
        int valid = M < MAXP ? M : MAXP;
        sValid = valid;
        if (valid < MAXP) {   // practically never taken
            int need = MAXP - valid, got = 0;
            for (int i = 0; i < NPTS && got < need; i++) {
                bool isP = false;
                for (int q = 0; q < valid; q++) {
                    int pidx = (int)(~(unsigned)(sk[q] & 0xFFFFFFFFu));
                    if (pidx == i) { isP = true; break; }
                }
                if (!isP) { fill[valid + got] = i; got++; }
            }
        }
    }
    __syncthreads();

    if (t < MAXP) {
        int valid = sValid;
        float sc; int idx;
        if (t < valid) {
            unsigned long long key = sk[t];
            sc  = __uint_as_float((unsigned)(key >> 32));
            idx = (int)(~(unsigned)(key & 0xFFFFFFFFu));
        } else {
            sc  = -1.0f;
            idx = fill[t];
        }
        out[NPTS + t]        = (float)idx;
        out[NPTS + MAXP + t] = sc;
        int cell = g_cell[idx];
        float* pc = out + NPTS + 2 * MAXP + (size_t)t * 4;
        pc[0] = (float)(cell >> 24);
        pc[1] = (float)((cell >> 15) & 511);
        pc[2] = (float)((cell >> 6) & 511);
        pc[3] = (float)(cell & 63);
    }
}

// ---------------- launch ----------------
extern "C" void kernel_launch(void* const* d_in, const int* in_sizes, int n_in,
                              void* d_out, int out_size) {
    const float* feats = (const float*)d_in[0];
    const int*   cb    = (const int*)  d_in[1];
    const int*   cx    = (const int*)  d_in[2];
    const int*   cy    = (const int*)  d_in[3];
    const int*   cz    = (const int*)  d_in[4];
    const int*   mask  = (const int*)  d_in[5];
    const float* W1    = (const float*)d_in[6];
    const float* b1    = (const float*)d_in[7];
    const float* W2    = (const float*)d_in[8];
    const float* b2    = (const float*)d_in[9];
    float* out = (float*)d_out;

    // cleanup of PREVIOUS replay's state runs first; no-op on the very first call.
    k_clean_grid<<<2048, 256>>>();
    k_prep<<<1, NBIN1>>>();
    k_mlp<<<(NPTS + 255) / 256, 256>>>(feats, cb, cx, cy, cz, mask,
                                       W1, b1, W2, b2, out);   // 3rd launch
    k_peak<<<2048, 256>>>();
    k_thresh<<<1, NBIN1>>>();
    k_compact<<<512, 256>>>();
    k_sortout<<<1, 1024>>>(out);
}

// round 13
// speedup vs baseline: 1.0482x; 1.0482x over previous
#include <cuda_runtime.h>
#include <cstdint>

// ---------------- problem constants ----------------
#define NPTS   1000000
#define FX     512
#define FY     512
#define FZ     64
#define FIN    64
#define FH     32
#define SCORE_T 0.1f
#define CENT_T  0.2f
#define MAXP    128
#define CCAP    2048
#define BIN1_BASE 0x3E4Cu      // float_bits(0.2) >> 16 ; peak scores in (0.2, 1.0)
#define NBIN1  512

// padded grid: [2][514][514][66], pad cells always 0
#define PX 514
#define PY 514
#define PZ 66
#define PCELLS (2*PX*PY*PZ)
#define DXS (PY*PZ)            // 33924
#define DYS (PZ)               // 66

// occupancy bitmap: one uint64 of z-bits per (b, x_padded, y_padded) -> 4.2 MB (L2-resident)
#define BMWORDS (2*PX*PY)

// ---------------- device scratch (zero-init at module load) ----------------
__device__ __align__(16) unsigned int g_grid[PCELLS];
__device__ unsigned long long g_bm[BMWORDS];    // bit z set iff cell (b,x,y,z) has s>0.1
__device__ int                g_cell[NPTS];     // packed coords (b<<24|x<<15|y<<6|z)
__device__ int                g_touch[NPTS];    // padded cells with s>0.1 (to reset)
__device__ unsigned long long g_cand[NPTS];     // s>0.2 candidates: (sb<<32)|~idx
__device__ int                g_ccellp[NPTS];   // padded cell per candidate
__device__ unsigned long long g_keys[NPTS];     // peaks
__device__ unsigned long long g_ckeys[CCAP];    // threshold survivors
__device__ __align__(16) int  g_hist1[NBIN1];
__device__ int g_touch_count, g_cand_count, g_peak_count, g_ccount;
__device__ unsigned int g_thresh;

// ---------------- f32x2 helpers ----------------
__device__ __forceinline__ unsigned long long pk2(float x) {
    unsigned long long r; unsigned xi = __float_as_uint(x);
    asm("mov.b64 %0, {%1, %1};" : "=l"(r) : "r"(xi));
    return r;
}
__device__ __forceinline__ void fma2(unsigned long long& d, unsigned long long a, unsigned long long b) {
    asm("fma.rn.f32x2 %0, %1, %2, %0;" : "+l"(d) : "l"(a), "l"(b));
}
__device__ __forceinline__ float2 up2(unsigned long long v) {
    unsigned a, b;
    asm("mov.b64 {%0, %1}, %2;" : "=r"(a), "=r"(b) : "l"(v));
    return make_float2(__uint_as_float(a), __uint_as_float(b));
}

// ---------------- K A1: cleanup grid + bitmap via prev replay's touch list --------
__global__ void __launch_bounds__(256) k_clean_grid()
{
    int tn  = g_touch_count;
    int gsz = gridDim.x * blockDim.x;
    for (int i = blockIdx.x * blockDim.x + threadIdx.x; i < tn; i += gsz) {
        int cellp = g_touch[i];
        g_grid[cellp] = 0u;
        g_bm[cellp / PZ] = 0ULL;     // idempotent word clear
    }
}

// ---------------- K A2: clear hist + reset counters (after clean_grid) ----------
__global__ void __launch_bounds__(NBIN1) k_prep()
{
    g_hist1[threadIdx.x] = 0;
    if (threadIdx.x == 0) {
        g_touch_count = 0; g_cand_count = 0; g_peak_count = 0; g_ccount = 0;
    }
}

// ---------------- K1: register-blocked GEMM MLP ----------------
__global__ void __launch_bounds__(256, 3) k_mlp(
    const float* __restrict__ feats,
    const int*   __restrict__ cb, const int* __restrict__ cx,
    const int*   __restrict__ cy, const int* __restrict__ cz,
    const int*   __restrict__ mask,
    const float* __restrict__ W1, const float* __restrict__ b1,
    const float* __restrict__ W2, const float* __restrict__ b2,
    float* __restrict__ out_score)
{
    __shared__ __align__(16) float4 sF4[256 * 8];   // 32 KB: one 32-feature chunk
    __shared__ __align__(16) float  sW1s[FIN * FH]; // 8 KB  [k][n]
    __shared__ __align__(16) float  sb1s[FH];
    __shared__ __align__(16) float  sW2s[FH];
    __shared__ float sb2s;

    int t = threadIdx.x;
    for (int i = t; i < FIN * FH; i += 256) sW1s[i] = W1[i];
    if (t < FH) { sb1s[t] = b1[t]; sW2s[t] = W2[t]; }
    if (t == 0) sb2s = b2[0];

    int blockBase = blockIdx.x * 256;
    int m_grp = t >> 3;            // 0..31
    int n_grp = t & 7;             // 0..7
    int sw    = 2 * (m_grp & 3);   // XOR swizzle for this thread's point rows

    const float4* F4 = reinterpret_cast<const float4*>(feats);

    // ---- stage chunk 0 (features 0..31) ----
    #pragma unroll
    for (int u = 0; u < 8; u++) {
        int lin = u * 256 + t;
        int p   = lin >> 3;
        int f4  = lin & 7;
        int gp  = blockBase + p; if (gp >= NPTS) gp = NPTS - 1;
        sF4[p * 8 + (f4 ^ (2 * ((p >> 3) & 3)))] = F4[(size_t)gp * 16 + f4];
    }
    __syncthreads();

    unsigned long long acc[16];
    {
        ulonglong2 binit = *reinterpret_cast<const ulonglong2*>(&sb1s[n_grp * 4]);
        #pragma unroll
        for (int pp = 0; pp < 8; pp++) { acc[2 * pp] = binit.x; acc[2 * pp + 1] = binit.y; }
    }

    // ---- consume chunk 0 (two 4-point halves to limit live registers) ----
    #pragma unroll
    for (int k4 = 0; k4 < 8; k4++) {
        ulonglong2 w0 = *reinterpret_cast<const ulonglong2*>(&sW1s[(k4 * 4 + 0) * FH + n_grp * 4]);
        ulonglong2 w1 = *reinterpret_cast<const ulonglong2*>(&sW1s[(k4 * 4 + 1) * FH + n_grp * 4]);
        ulonglong2 w2 = *reinterpret_cast<const ulonglong2*>(&sW1s[(k4 * 4 + 2) * FH + n_grp * 4]);
        ulonglong2 w3 = *reinterpret_cast<const ulonglong2*>(&sW1s[(k4 * 4 + 3) * FH + n_grp * 4]);
        #pragma unroll
        for (int h = 0; h < 2; h++) {
            #pragma unroll
            for (int pq = 0; pq < 4; pq++) {
                int pp = h * 4 + pq;
                float4 fv = sF4[(m_grp * 8 + pp) * 8 + (k4 ^ sw)];
                unsigned long long fp;
                fp = pk2(fv.x); fma2(acc[2*pp], fp, w0.x); fma2(acc[2*pp+1], fp, w0.y);
                fp = pk2(fv.y); fma2(acc[2*pp], fp, w1.x); fma2(acc[2*pp+1], fp, w1.y);
                fp = pk2(fv.z); fma2(acc[2*pp], fp, w2.x); fma2(acc[2*pp+1], fp, w2.y);
                fp = pk2(fv.w); fma2(acc[2*pp], fp, w3.x); fma2(acc[2*pp+1], fp, w3.y);
            }
        }
    }
    __syncthreads();

    // ---- stage chunk 1 (features 32..63) ----
    #pragma unroll
    for (int u = 0; u < 8; u++) {
        int lin = u * 256 + t;
        int p   = lin >> 3;
        int f4  = lin & 7;
        int gp  = blockBase + p; if (gp >= NPTS) gp = NPTS - 1;
        sF4[p * 8 + (f4 ^ (2 * ((p >> 3) & 3)))] = F4[(size_t)gp * 16 + 8 + f4];
    }
    __syncthreads();

    // ---- consume chunk 1 ----
    #pragma unroll
    for (int k4 = 0; k4 < 8; k4++) {
        ulonglong2 w0 = *reinterpret_cast<const ulonglong2*>(&sW1s[(32 + k4 * 4 + 0) * FH + n_grp * 4]);
        ulonglong2 w1 = *reinterpret_cast<const ulonglong2*>(&sW1s[(32 + k4 * 4 + 1) * FH + n_grp * 4]);
        ulonglong2 w2 = *reinterpret_cast<const ulonglong2*>(&sW1s[(32 + k4 * 4 + 2) * FH + n_grp * 4]);
        ulonglong2 w3 = *reinterpret_cast<const ulonglong2*>(&sW1s[(32 + k4 * 4 + 3) * FH + n_grp * 4]);
        #pragma unroll
        for (int h = 0; h < 2; h++) {
            #pragma unroll
            for (int pq = 0; pq < 4; pq++) {
                int pp = h * 4 + pq;
                float4 fv = sF4[(m_grp * 8 + pp) * 8 + (k4 ^ sw)];
                unsigned long long fp;
                fp = pk2(fv.x); fma2(acc[2*pp], fp, w0.x); fma2(acc[2*pp+1], fp, w0.y);
                fp = pk2(fv.y); fma2(acc[2*pp], fp, w1.x); fma2(acc[2*pp+1], fp, w1.y);
                fp = pk2(fv.z); fma2(acc[2*pp], fp, w2.x); fma2(acc[2*pp+1], fp, w2.y);
                fp = pk2(fv.w); fma2(acc[2*pp], fp, w3.x); fma2(acc[2*pp+1], fp, w3.y);
            }
        }
    }

    // ---- second layer: per-thread partial over its 4 cols, butterfly over n_grp ----
    float4 w2v = *reinterpret_cast<const float4*>(&sW2s[n_grp * 4]);
    float part[8];
    #pragma unroll
    for (int pp = 0; pp < 8; pp++) {
        float2 a0 = up2(acc[2 * pp]);
        float2 a1 = up2(acc[2 * pp + 1]);
        float p0 = fmaxf(a0.x, 0.0f) * w2v.x;
        p0 = fmaf(fmaxf(a0.y, 0.0f), w2v.y, p0);
        p0 = fmaf(fmaxf(a1.x, 0.0f), w2v.z, p0);
        p0 = fmaf(fmaxf(a1.y, 0.0f), w2v.w, p0);
        part[pp] = p0;
    }
    #pragma unroll
    for (int off = 1; off < 8; off <<= 1) {
        #pragma unroll
        for (int pp = 0; pp < 8; pp++)
            part[pp] += __shfl_xor_sync(0xFFFFFFFFu, part[pp], off);
    }
    float z = part[n_grp] + sb2s;   // lane's point = blockBase + t

    // ---- epilogue ----
    int i = blockBase + t;
    bool valid = (i < NPTS);
    float s = 0.0f;
    int cellp = 0;
    int zc = 0;
    unsigned sb = 0u;
    if (valid) {
        s = 1.0f / (1.0f + expf(-z));
        if (mask[i] == 0) s = 0.0f;
        out_score[i] = s;
        int b = cb[i], x = cx[i], y = cy[i];
        zc = cz[i];
        g_cell[i] = (b << 24) | (x << 15) | (y << 6) | zc;
        cellp = ((b * PX + x + 1) * PY + y + 1) * PZ + (zc + 1);
        sb = __float_as_uint(s);
    }
    int lane = t & 31;

    bool dep = valid && (s > SCORE_T);
    if (dep) {
        atomicMax(&g_grid[cellp], sb);
        atomicOr(&g_bm[cellp / PZ], 1ULL << zc);
    }
    unsigned m = __ballot_sync(0xFFFFFFFFu, dep);
    int base = 0;
    if (lane == 0 && m) base = atomicAdd(&g_touch_count, __popc(m));
    base = __shfl_sync(0xFFFFFFFFu, base, 0);
    if (dep) g_touch[base + __popc(m & ((1u << lane) - 1u))] = cellp;

    bool cnd = valid && (s > CENT_T);
    unsigned m2 = __ballot_sync(0xFFFFFFFFu, cnd);
    int base2 = 0;
    if (lane == 0 && m2) base2 = atomicAdd(&g_cand_count, __popc(m2));
    base2 = __shfl_sync(0xFFFFFFFFu, base2, 0);
    if (cnd) {
        int pos = base2 + __popc(m2 & ((1u << lane) - 1u));
        g_cand[pos]   = ((unsigned long long)sb << 32) | (unsigned)(~(unsigned)i);
        g_ccellp[pos] = cellp;
    }
}

// ---------------- K2: peak detect via L2-resident occupancy bitmap ----------------
__global__ void __launch_bounds__(256) k_peak()
{
    int n   = g_cand_count;
    int gsz = gridDim.x * blockDim.x;
    int idx = blockIdx.x * blockDim.x + threadIdx.x;
    int iters = (n + gsz - 1) / gsz;
    int lane = threadIdx.x & 31;

    for (int it = 0; it < iters; it++, idx += gsz) {
        bool valid = (idx < n);
        unsigned long long key = 0ULL;
        unsigned sb = 0u, hmax = 0u;
        if (valid) {
            key = g_cand[idx];
            sb  = (unsigned)(key >> 32);
            int cp    = g_ccellp[idx];
            int word0 = cp / PZ;                 // (b*PX + x+1)*PY + (y+1)
            int zc    = cp - word0 * PZ - 1;     // original z, 0..63
            unsigned long long zmask = (zc == 0) ? 3ULL : (7ULL << (zc - 1));
            #pragma unroll
            for (int dx = -1; dx <= 1; dx++) {
                #pragma unroll
                for (int dy = -1; dy <= 1; dy++) {
                    int w = word0 + dx * PY + dy;
                    unsigned long long bits = g_bm[w] & zmask;   // L2 hit (4.2 MB map)
                    while (bits) {
                        int j = __ffsll(bits) - 1;
                        bits &= bits - 1;
                        unsigned v = g_grid[w * PZ + j + 1];     // only occupied cells
                        hmax = v > hmax ? v : hmax;
                    }
                }
            }
        }
        bool isPeak = valid && (hmax == sb);
        unsigned m = __ballot_sync(0xFFFFFFFFu, isPeak);
        int base = 0;
        if (lane == 0 && m) base = atomicAdd(&g_peak_count, __popc(m));
        base = __shfl_sync(0xFFFFFFFFu, base, 0);
        if (isPeak) {
            g_keys[base + __popc(m & ((1u << lane) - 1u))] = key;
            atomicAdd(&g_hist1[(sb >> 16) - BIN1_BASE], 1);
        }
    }
}

// ---------------- K3: single-level threshold (1 block, 512 thr) ----------------
__global__ void __launch_bounds__(NBIN1) k_thresh()
{
    __shared__ int csum[NBIN1];
    int t = threadIdx.x;
    int h = g_hist1[t];
    csum[t] = h;
    __syncthreads();
    for (int off = 1; off < NBIN1; off <<= 1) {
        int v = (t >= off) ? csum[t - off] : 0;
        __syncthreads();
        csum[t] += v;
        __syncthreads();
    }
    int total = csum[NBIN1 - 1];
    if (total < MAXP) {
        if (t == 0) g_thresh = 0u;      // take all peaks
        return;
    }
    int above = total - csum[t];        // strictly above bin t
    if (above < MAXP && above + h >= MAXP)
        g_thresh = ((unsigned)(t + BIN1_BASE)) << 16;
}

// ---------------- K4: compact survivors (grid-wide) ----------------
__global__ void __launch_bounds__(256) k_compact()
{
    int n = g_peak_count;
    unsigned th = g_thresh;
    int gsz = gridDim.x * blockDim.x;
    int idx = blockIdx.x * blockDim.x + threadIdx.x;
    int iters = (n + gsz - 1) / gsz;
    int lane = threadIdx.x & 31;
    for (int it = 0; it < iters; it++, idx += gsz) {
        bool take = false;
        unsigned long long key = 0ULL;
        if (idx < n) {
            key = g_keys[idx];
            take = ((unsigned)(key >> 32) >= th);
        }
        unsigned m = __ballot_sync(0xFFFFFFFFu, take);
        int base = 0;
        if (lane == 0 && m) base = atomicAdd(&g_ccount, __popc(m));
        base = __shfl_sync(0xFFFFFFFFu, base, 0);
        if (take) {
            int pos = base + __popc(m & ((1u << lane) - 1u));
            if (pos < CCAP) g_ckeys[pos] = key;
        }
    }
}

// ---------------- K5: sort 2048 + emit outputs (1 block, 1024 thr) ----------------
__global__ void __launch_bounds__(1024) k_sortout(float* __restrict__ out)
{
    __shared__ unsigned long long sk[CCAP];     // 16 KB
    __shared__ int fill[MAXP];
    __shared__ int sValid;
    int t = threadIdx.x;
    int M = g_ccount; if (M > CCAP) M = CCAP;
    sk[t]        = (t        < M) ? g_ckeys[t]        : 0ULL;
    sk[t + 1024] = (t + 1024 < M) ? g_ckeys[t + 1024] : 0ULL;
    __syncthreads();

    // bitonic sort, descending (2048 elems, 2/thread)
    for (int kk = 2; kk <= CCAP; kk <<= 1) {
        for (int j = kk >> 1; j > 0; j >>= 1) {
            #pragma unroll
            for (int half = 0; half < 2; half++) {
                int i = t + half * 1024;
                int ixj = i ^ j;
                if (ixj > i) {
                    unsigned long long a = sk[i], b = sk[ixj];
                    bool desc = ((i & kk) == 0);
                    if (desc ? (a < b) : (a > b)) { sk[i] = b; sk[ixj] = a; }
                }
            }
            __syncthreads();
        }
    }

    if (t == 0) {
        int valid = M < MAXP ? M : MAXP;
        sValid = valid;
        if (valid < MAXP) {   // practically never taken
            int need = MAXP - valid, got = 0;
            for (int i = 0; i < NPTS && got < need; i++) {
                bool isP = false;
                for (int q = 0; q < valid; q++) {
                    int pidx = (int)(~(unsigned)(sk[q] & 0xFFFFFFFFu));
                    if (pidx == i) { isP = true; break; }
                }
                if (!isP) { fill[valid + got] = i; got++; }
            }
        }
    }
    __syncthreads();

    if (t < MAXP) {
        int valid = sValid;
        float sc; int idx;
        if (t < valid) {
            unsigned long long key = sk[t];
            sc  = __uint_as_float((unsigned)(key >> 32));
            idx = (int)(~(unsigned)(key & 0xFFFFFFFFu));
        } else {
            sc  = -1.0f;
            idx = fill[t];
        }
        out[NPTS + t]        = (float)idx;
        out[NPTS + MAXP + t] = sc;
        int cell = g_cell[idx];
        float* pc = out + NPTS + 2 * MAXP + (size_t)t * 4;
        pc[0] = (float)(cell >> 24);
        pc[1] = (float)((cell >> 15) & 511);
        pc[2] = (float)((cell >> 6) & 511);
        pc[3] = (float)(cell & 63);
    }
}

// ---------------- launch ----------------
extern "C" void kernel_launch(void* const* d_in, const int* in_sizes, int n_in,
                              void* d_out, int out_size) {
    const float* feats = (const float*)d_in[0];
    const int*   cb    = (const int*)  d_in[1];
    const int*   cx    = (const int*)  d_in[2];
    const int*   cy    = (const int*)  d_in[3];
    const int*   cz    = (const int*)  d_in[4];
    const int*   mask  = (const int*)  d_in[5];
    const float* W1    = (const float*)d_in[6];
    const float* b1    = (const float*)d_in[7];
    const float* W2    = (const float*)d_in[8];
    const float* b2    = (const float*)d_in[9];
    float* out = (float*)d_out;

    // cleanup of PREVIOUS replay's state runs first; no-op on the very first call.
    k_clean_grid<<<2048, 256>>>();
    k_prep<<<1, NBIN1>>>();
    k_mlp<<<(NPTS + 255) / 256, 256>>>(feats, cb, cx, cy, cz, mask,
                                       W1, b1, W2, b2, out);
    k_peak<<<2048, 256>>>();           // 4th launch -> ncu verifies bitmap theory
    k_thresh<<<1, NBIN1>>>();
    k_compact<<<512, 256>>>();
    k_sortout<<<1, 1024>>>(out);
}

// round 15
// speedup vs baseline: 1.0622x; 1.0134x over previous
#include <cuda_runtime.h>
#include <cstdint>

// ---------------- problem constants ----------------
#define NPTS   1000000
#define FX     512
#define FY     512
#define FZ     64
#define FIN    64
#define FH     32
#define SCORE_T 0.1f
#define CENT_T  0.2f
#define MAXP    128
#define CCAP    2048
#define BIN1_BASE 0x3E4Cu      // float_bits(0.2) >> 16 ; peak scores in (0.2, 1.0)
#define NBIN1  512

// padded grid: [2][514][514][66], pad cells always 0
#define PX 514
#define PY 514
#define PZ 66
#define PCELLS (2*PX*PY*PZ)
#define DXS (PY*PZ)            // 33924
#define DYS (PZ)               // 66

// occupancy bitmap: one uint64 of z-bits per (b, x_padded, y_padded) -> 4.2 MB (L2-resident)
#define BMWORDS (2*PX*PY)

// ---------------- device scratch (zero-init at module load) ----------------
__device__ __align__(16) unsigned int g_grid[PCELLS];
__device__ unsigned long long g_bm[BMWORDS];    // bit z set iff cell (b,x,y,z) has s>0.1
__device__ int                g_cell[NPTS];     // packed coords (b<<24|x<<15|y<<6|z)
__device__ int                g_touch[NPTS];    // padded cells with s>0.1 (to reset)
__device__ unsigned long long g_cand[NPTS];     // s>0.2 candidates: (sb<<32)|~idx
__device__ int                g_ccellp[NPTS];   // padded cell per candidate
__device__ unsigned long long g_keys[NPTS];     // peaks
__device__ unsigned long long g_ckeys[CCAP];    // threshold survivors
__device__ __align__(16) int  g_hist1[NBIN1];
__device__ int g_touch_count, g_cand_count, g_peak_count, g_ccount;
__device__ unsigned int g_thresh;

// ---------------- f32x2 / cp.async helpers ----------------
__device__ __forceinline__ unsigned long long pk2(float x) {
    unsigned long long r; unsigned xi = __float_as_uint(x);
    asm("mov.b64 %0, {%1, %1};" : "=l"(r) : "r"(xi));
    return r;
}
__device__ __forceinline__ void fma2(unsigned long long& d, unsigned long long a, unsigned long long b) {
    asm("fma.rn.f32x2 %0, %1, %2, %0;" : "+l"(d) : "l"(a), "l"(b));
}
__device__ __forceinline__ float2 up2(unsigned long long v) {
    unsigned a, b;
    asm("mov.b64 {%0, %1}, %2;" : "=r"(a), "=r"(b) : "l"(v));
    return make_float2(__uint_as_float(a), __uint_as_float(b));
}
__device__ __forceinline__ unsigned smem_u32(const void* p) {
    unsigned a;
    asm("{ .reg .u64 t; cvta.to.shared.u64 t, %1; cvt.u32.u64 %0, t; }" : "=r"(a) : "l"(p));
    return a;
}
#define CP_ASYNC16(dst, src) \
    asm volatile("cp.async.cg.shared.global [%0], [%1], 16;" :: "r"(dst), "l"(src))
#define CP_COMMIT()  asm volatile("cp.async.commit_group;" ::: "memory")
#define CP_WAIT1()   asm volatile("cp.async.wait_group 1;" ::: "memory")
#define CP_WAIT0()   asm volatile("cp.async.wait_group 0;" ::: "memory")

// ---------------- K A1: cleanup grid + bitmap via prev replay's touch list --------
__global__ void __launch_bounds__(256) k_clean_grid()
{
    int tn  = g_touch_count;
    int gsz = gridDim.x * blockDim.x;
    for (int i = blockIdx.x * blockDim.x + threadIdx.x; i < tn; i += gsz) {
        int cellp = g_touch[i];
        g_grid[cellp] = 0u;
        g_bm[cellp / PZ] = 0ULL;     // idempotent word clear
    }
}

// ---------------- K A2: clear hist ----------------
__global__ void __launch_bounds__(NBIN1) k_clean_hist()
{
    g_hist1[threadIdx.x] = 0;
}

// ---------------- K A3: reset counters ----------------
__global__ void k_reset()
{
    if (threadIdx.x == 0) {
        g_touch_count = 0; g_cand_count = 0; g_peak_count = 0; g_ccount = 0;
    }
}

// ---------------- K1 (4th launch -> ncu): cp.async double-buffered GEMM MLP -------
// 4 chunks x 16 features, staged via cp.async into 2 x 16 KB buffers.
// Wait discipline (FIXED): prefetch chunks 0,1; per iter stage c+1 (c>=1),
// CP_WAIT1 -> group c complete, sync, consume, sync.
__global__ void __launch_bounds__(256) k_mlp(
    const float* __restrict__ feats,
    const int*   __restrict__ cb, const int* __restrict__ cx,
    const int*   __restrict__ cy, const int* __restrict__ cz,
    const int*   __restrict__ mask,
    const float* __restrict__ W1, const float* __restrict__ b1,
    const float* __restrict__ W2, const float* __restrict__ b2,
    float* __restrict__ out_score)
{
    __shared__ __align__(16) float4 sF4[2][256 * 4];   // 2 x 16 KB staging
    __shared__ __align__(16) float  sW1s[FIN * FH];    // 8 KB [k][n]
    __shared__ __align__(16) float  sb1s[FH];
    __shared__ __align__(16) float  sW2s[FH];
    __shared__ float sb2s;

    int t = threadIdx.x;
    for (int i = t; i < FIN * FH; i += 256) sW1s[i] = W1[i];
    if (t < FH) { sb1s[t] = b1[t]; sW2s[t] = W2[t]; }
    if (t == 0) sb2s = b2[0];

    int blockBase = blockIdx.x * 256;
    int m_grp = t >> 3;            // 0..31
    int n_grp = t & 7;             // 0..7
    int sw    = m_grp & 3;         // slot XOR swizzle

    const float4* F4 = reinterpret_cast<const float4*>(feats);
    unsigned sbase = smem_u32(&sF4[0][0]);

    // stage chunk c (16 features = 4 float4/point) into buffer buf; one group per call
    auto stage = [&](int c, int buf) {
        #pragma unroll
        for (int u = 0; u < 4; u++) {
            int lin = u * 256 + t;          // 0..1023
            int p   = lin >> 2;             // local point
            int f   = lin & 3;              // float4 slot in chunk
            int gp  = blockBase + p; if (gp >= NPTS) gp = NPTS - 1;
            const float4* src = F4 + (size_t)gp * 16 + c * 4 + f;
            unsigned dst = sbase + (unsigned)(buf * 1024 + p * 4 + (f ^ ((p >> 3) & 3))) * 16u;
            CP_ASYNC16(dst, src);
        }
        CP_COMMIT();
    };

    // prefetch chunks 0 and 1 (groups 0 and 1)
    stage(0, 0);
    stage(1, 1);

    __syncthreads();   // weights/bias visible (barrier does not wait on cp.async)

    unsigned long long acc[16];
    {
        ulonglong2 binit = *reinterpret_cast<const ulonglong2*>(&sb1s[n_grp * 4]);
        #pragma unroll
        for (int pp = 0; pp < 8; pp++) { acc[2 * pp] = binit.x; acc[2 * pp + 1] = binit.y; }
    }

    #pragma unroll
    for (int c = 0; c < 4; c++) {
        int buf = c & 1;
        if (c >= 1 && c + 1 < 4) stage(c + 1, (c + 1) & 1);  // refill buf consumed last iter
        if (c < 3) CP_WAIT1(); else CP_WAIT0();              // group c complete
        __syncthreads();                                     // cross-thread visibility
        // consume chunk c: 4 k-groups of 4 features
        #pragma unroll
        for (int j = 0; j < 4; j++) {
            int f0 = c * 16 + j * 4;
            ulonglong2 w0 = *reinterpret_cast<const ulonglong2*>(&sW1s[(f0 + 0) * FH + n_grp * 4]);
            ulonglong2 w1 = *reinterpret_cast<const ulonglong2*>(&sW1s[(f0 + 1) * FH + n_grp * 4]);
            ulonglong2 w2 = *reinterpret_cast<const ulonglong2*>(&sW1s[(f0 + 2) * FH + n_grp * 4]);
            ulonglong2 w3 = *reinterpret_cast<const ulonglong2*>(&sW1s[(f0 + 3) * FH + n_grp * 4]);
            #pragma unroll
            for (int pp = 0; pp < 8; pp++) {
                float4 fv = sF4[buf][(m_grp * 8 + pp) * 4 + (j ^ sw)];
                unsigned long long fp;
                fp = pk2(fv.x); fma2(acc[2*pp], fp, w0.x); fma2(acc[2*pp+1], fp, w0.y);
                fp = pk2(fv.y); fma2(acc[2*pp], fp, w1.x); fma2(acc[2*pp+1], fp, w1.y);
                fp = pk2(fv.z); fma2(acc[2*pp], fp, w2.x); fma2(acc[2*pp+1], fp, w2.y);
                fp = pk2(fv.w); fma2(acc[2*pp], fp, w3.x); fma2(acc[2*pp+1], fp, w3.y);
            }
        }
        __syncthreads();   // all threads done with buf before next-iter refill
    }

    // ---- second layer: per-thread partial over its 4 cols, butterfly over n_grp ----
    float4 w2v = *reinterpret_cast<const float4*>(&sW2s[n_grp * 4]);
    float part[8];
    #pragma unroll
    for (int pp = 0; pp < 8; pp++) {
        float2 a0 = up2(acc[2 * pp]);
        float2 a1 = up2(acc[2 * pp + 1]);
        float p0 = fmaxf(a0.x, 0.0f) * w2v.x;
        p0 = fmaf(fmaxf(a0.y, 0.0f), w2v.y, p0);
        p0 = fmaf(fmaxf(a1.x, 0.0f), w2v.z, p0);
        p0 = fmaf(fmaxf(a1.y, 0.0f), w2v.w, p0);
        part[pp] = p0;
    }
    #pragma unroll
    for (int off = 1; off < 8; off <<= 1) {
        #pragma unroll
        for (int pp = 0; pp < 8; pp++)
            part[pp] += __shfl_xor_sync(0xFFFFFFFFu, part[pp], off);
    }
    float z = part[n_grp] + sb2s;   // lane's point = blockBase + t

    // ---- epilogue ----
    int i = blockBase + t;
    bool valid = (i < NPTS);
    float s = 0.0f;
    int cellp = 0;
    int zc = 0;
    unsigned sb = 0u;
    if (valid) {
        s = 1.0f / (1.0f + expf(-z));
        if (mask[i] == 0) s = 0.0f;
        out_score[i] = s;
        int b = cb[i], x = cx[i], y = cy[i];
        zc = cz[i];
        g_cell[i] = (b << 24) | (x << 15) | (y << 6) | zc;
        cellp = ((b * PX + x + 1) * PY + y + 1) * PZ + (zc + 1);
        sb = __float_as_uint(s);
    }
    int lane = t & 31;

    bool dep = valid && (s > SCORE_T);
    if (dep) {
        atomicMax(&g_grid[cellp], sb);
        atomicOr(&g_bm[cellp / PZ], 1ULL << zc);
    }
    unsigned m = __ballot_sync(0xFFFFFFFFu, dep);
    int base = 0;
    if (lane == 0 && m) base = atomicAdd(&g_touch_count, __popc(m));
    base = __shfl_sync(0xFFFFFFFFu, base, 0);
    if (dep) g_touch[base + __popc(m & ((1u << lane) - 1u))] = cellp;

    bool cnd = valid && (s > CENT_T);
    unsigned m2 = __ballot_sync(0xFFFFFFFFu, cnd);
    int base2 = 0;
    if (lane == 0 && m2) base2 = atomicAdd(&g_cand_count, __popc(m2));
    base2 = __shfl_sync(0xFFFFFFFFu, base2, 0);
    if (cnd) {
        int pos = base2 + __popc(m2 & ((1u << lane) - 1u));
        g_cand[pos]   = ((unsigned long long)sb << 32) | (unsigned)(~(unsigned)i);
        g_ccellp[pos] = cellp;
    }
}

// ---------------- K2: peak detect — batched bitmap loads, then bit probes ---------
__global__ void __launch_bounds__(256) k_peak()
{
    int n   = g_cand_count;
    int gsz = gridDim.x * blockDim.x;
    int idx = blockIdx.x * blockDim.x + threadIdx.x;
    int iters = (n + gsz - 1) / gsz;
    int lane = threadIdx.x & 31;

    for (int it = 0; it < iters; it++, idx += gsz) {
        bool valid = (idx < n);
        unsigned long long key = 0ULL;
        unsigned sb = 0u, hmax = 0u;
        if (valid) {
            key = g_cand[idx];
            sb  = (unsigned)(key >> 32);
            int cp    = g_ccellp[idx];
            int word0 = cp / PZ;
            int zc    = cp - word0 * PZ - 1;     // original z, 0..63
            unsigned long long zmask = (zc == 0) ? 3ULL : (7ULL << (zc - 1));

            // batch all 9 bitmap loads (independent; one L2 round-trip)
            unsigned long long bw[9];
            int wd[9];
            #pragma unroll
            for (int dx = 0; dx < 3; dx++)
                #pragma unroll
                for (int dy = 0; dy < 3; dy++) {
                    int w = word0 + (dx - 1) * PY + (dy - 1);
                    wd[dx * 3 + dy] = w;
                    bw[dx * 3 + dy] = g_bm[w];
                }
            #pragma unroll
            for (int q = 0; q < 9; q++) {
                unsigned long long bits = bw[q] & zmask;
                while (bits) {
                    int j = __ffsll(bits) - 1;
                    bits &= bits - 1;
                    unsigned v = g_grid[wd[q] * PZ + j + 1];
                    hmax = v > hmax ? v : hmax;
                }
            }
        }
        bool isPeak = valid && (hmax == sb);
        unsigned m = __ballot_sync(0xFFFFFFFFu, isPeak);
        int base = 0;
        if (lane == 0 && m) base = atomicAdd(&g_peak_count, __popc(m));
        base = __shfl_sync(0xFFFFFFFFu, base, 0);
        if (isPeak) {
            g_keys[base + __popc(m & ((1u << lane) - 1u))] = key;
            atomicAdd(&g_hist1[(sb >> 16) - BIN1_BASE], 1);
        }
    }
}

// ---------------- K3: single-level threshold (1 block, 512 thr) ----------------
__global__ void __launch_bounds__(NBIN1) k_thresh()
{
    __shared__ int csum[NBIN1];
    int t = threadIdx.x;
    int h = g_hist1[t];
    csum[t] = h;
    __syncthreads();
    for (int off = 1; off < NBIN1; off <<= 1) {
        int v = (t >= off) ? csum[t - off] : 0;
        __syncthreads();
        csum[t] += v;
        __syncthreads();
    }
    int total = csum[NBIN1 - 1];
    if (total < MAXP) {
        if (t == 0) g_thresh = 0u;      // take all peaks
        return;
    }
    int above = total - csum[t];        // strictly above bin t
    if (above < MAXP && above + h >= MAXP)
        g_thresh = ((unsigned)(t + BIN1_BASE)) << 16;
}

// ---------------- K4: compact survivors (grid-wide) ----------------
__global__ void __launch_bounds__(256) k_compact()
{
    int n = g_peak_count;
    unsigned th = g_thresh;
    int gsz = gridDim.x * blockDim.x;
    int idx = blockIdx.x * blockDim.x + threadIdx.x;
    int iters = (n + gsz - 1) / gsz;
    int lane = threadIdx.x & 31;
    for (int it = 0; it < iters; it++, idx += gsz) {
        bool take = false;
        unsigned long long key = 0ULL;
        if (idx < n) {
            key = g_keys[idx];
            take = ((unsigned)(key >> 32) >= th);
        }
        unsigned m = __ballot_sync(0xFFFFFFFFu, take);
        int base = 0;
        if (lane == 0 && m) base = atomicAdd(&g_ccount, __popc(m));
        base = __shfl_sync(0xFFFFFFFFu, base, 0);
        if (take) {
            int pos = base + __popc(m & ((1u << lane) - 1u));
            if (pos < CCAP) g_ckeys[pos] = key;
        }
    }
}

// ---------------- K5: sort 2048 + emit outputs (1 block, 1024 thr) ----------------
__global__ void __launch_bounds__(1024) k_sortout(float* __restrict__ out)
{
    __shared__ unsigned long long sk[CCAP];     // 16 KB
    __shared__ int fill[MAXP];
    __shared__ int sValid;
    int t = threadIdx.x;
    int M = g_ccount; if (M > CCAP) M = CCAP;
    sk[t]        = (t        < M) ? g_ckeys[t]        : 0ULL;
    sk[t + 1024] = (t + 1024 < M) ? g_ckeys[t + 1024] : 0ULL;
    __syncthreads();

    // bitonic sort, descending (2048 elems, 2/thread)
    for (int kk = 2; kk <= CCAP; kk <<= 1) {
        for (int j = kk >> 1; j > 0; j >>= 1) {
            #pragma unroll
            for (int half = 0; half < 2; half++) {
                int i = t + half * 1024;
                int ixj = i ^ j;
                if (ixj > i) {
                    unsigned long long a = sk[i], b = sk[ixj];
                    bool desc = ((i & kk) == 0);
                    if (desc ? (a < b) : (a > b)) { sk[i] = b; sk[ixj] = a; }
                }
            }
            __syncthreads();
        }
    }

    if (t == 0) {
        int valid = M < MAXP ? M : MAXP;
        sValid = valid;
        if (valid < MAXP) {   // practically never taken
            int need = MAXP - valid, got = 0;
            for (int i = 0; i < NPTS && got < need; i++) {
                bool isP = false;
                for (int q = 0; q < valid; q++) {
                    int pidx = (int)(~(unsigned)(sk[q] & 0xFFFFFFFFu));
                    if (pidx == i) { isP = true; break; }
                }
                if (!isP) { fill[valid + got] = i; got++; }
            }
        }
    }
    __syncthreads();

    if (t < MAXP) {
        int valid = sValid;
        float sc; int idx;
        if (t < valid) {
            unsigned long long key = sk[t];
            sc  = __uint_as_float((unsigned)(key >> 32));
            idx = (int)(~(unsigned)(key & 0xFFFFFFFFu));
        } else {
            sc  = -1.0f;
            idx = fill[t];
        }
        out[NPTS + t]        = (float)idx;
        out[NPTS + MAXP + t] = sc;
        int cell = g_cell[idx];
        float* pc = out + NPTS + 2 * MAXP + (size_t)t * 4;
        pc[0] = (float)(cell >> 24);
        pc[1] = (float)((cell >> 15) & 511);
        pc[2] = (float)((cell >> 6) & 511);
        pc[3] = (float)(cell & 63);
    }
}

// ---------------- launch ----------------
extern "C" void kernel_launch(void* const* d_in, const int* in_sizes, int n_in,
                              void* d_out, int out_size) {
    const float* feats = (const float*)d_in[0];
    const int*   cb    = (const int*)  d_in[1];
    const int*   cx    = (const int*)  d_in[2];
    const int*   cy    = (const int*)  d_in[3];
    const int*   cz    = (const int*)  d_in[4];
    const int*   mask  = (const int*)  d_in[5];
    const float* W1    = (const float*)d_in[6];
    const float* b1    = (const float*)d_in[7];
    const float* W2    = (const float*)d_in[8];
    const float* b2    = (const float*)d_in[9];
    float* out = (float*)d_out;

    // cleanup of PREVIOUS replay's state runs first; no-op on the very first call.
    k_clean_grid<<<2048, 256>>>();
    k_clean_hist<<<1, NBIN1>>>();
    k_reset<<<1, 32>>>();
    k_mlp<<<(NPTS + 255) / 256, 256>>>(feats, cb, cx, cy, cz, mask,
                                       W1, b1, W2, b2, out);   // 4th launch -> ncu
    k_peak<<<2048, 256>>>();
    k_thresh<<<1, NBIN1>>>();
    k_compact<<<512, 256>>>();
    k_sortout<<<1, 1024>>>(out);
}

// round 17
// speedup vs baseline: 1.0759x; 1.0129x over previous
#include <cuda_runtime.h>
#include <cstdint>

// ---------------- problem constants ----------------
#define NPTS   1000000
#define FX     512
#define FY     512
#define FZ     64
#define FIN    64
#define FH     32
#define SCORE_T 0.1f
#define CENT_T  0.2f
#define MAXP    128
#define CCAP    2048
#define BIN1_BASE 0x3E4Cu      // float_bits(0.2) >> 16 ; peak scores in (0.2, 1.0)
#define NBIN1  512

// padded grid: [2][514][514][66], pad cells always 0
#define PX 514
#define PY 514
#define PZ 66
#define PCELLS (2*PX*PY*PZ)
#define DXS (PY*PZ)            // 33924
#define DYS (PZ)               // 66

// occupancy bitmap: one uint64 of z-bits per (b, x_padded, y_padded) -> 4.2 MB (L2-resident)
#define BMWORDS (2*PX*PY)

#define MLPB 128               // k_mlp threads/block
#define WPB  4                 // warps/block

// ---------------- device scratch (zero-init at module load) ----------------
__device__ __align__(16) unsigned int g_grid[PCELLS];
__device__ unsigned long long g_bm[BMWORDS];    // bit z set iff cell (b,x,y,z) has s>0.1
__device__ int                g_cell[NPTS];     // packed coords (b<<24|x<<15|y<<6|z)
__device__ int                g_touch[NPTS];    // padded cells with s>0.1 (to reset)
__device__ unsigned long long g_cand[NPTS];     // s>0.2 candidates: (sb<<32)|~idx
__device__ int                g_ccellp[NPTS];   // padded cell per candidate
__device__ unsigned long long g_keys[NPTS];     // peaks
__device__ unsigned long long g_ckeys[CCAP];    // threshold survivors
__device__ __align__(16) int  g_hist1[NBIN1];
__device__ int g_touch_count, g_cand_count, g_peak_count, g_ccount;
__device__ unsigned int g_thresh;

// ---------------- f32x2 / cp.async helpers ----------------
__device__ __forceinline__ unsigned long long pk2(float x) {
    unsigned long long r; unsigned xi = __float_as_uint(x);
    asm("mov.b64 %0, {%1, %1};" : "=l"(r) : "r"(xi));
    return r;
}
__device__ __forceinline__ void fma2(unsigned long long& d, unsigned long long a, unsigned long long b) {
    asm("fma.rn.f32x2 %0, %1, %2, %0;" : "+l"(d) : "l"(a), "l"(b));
}
__device__ __forceinline__ float2 up2(unsigned long long v) {
    unsigned a, b;
    asm("mov.b64 {%0, %1}, %2;" : "=r"(a), "=r"(b) : "l"(v));
    return make_float2(__uint_as_float(a), __uint_as_float(b));
}
__device__ __forceinline__ unsigned smem_u32(const void* p) {
    unsigned a;
    asm("{ .reg .u64 t; cvta.to.shared.u64 t, %1; cvt.u32.u64 %0, t; }" : "=r"(a) : "l"(p));
    return a;
}
#define CP_ASYNC16(dst, src) \
    asm volatile("cp.async.cg.shared.global [%0], [%1], 16;" :: "r"(dst), "l"(src))
#define CP_COMMIT()  asm volatile("cp.async.commit_group;" ::: "memory")
#define CP_WAIT1()   asm volatile("cp.async.wait_group 1;" ::: "memory")
#define CP_WAIT0()   asm volatile("cp.async.wait_group 0;" ::: "memory")

// ---------------- K A1: cleanup grid + bitmap via prev replay's touch list --------
__global__ void __launch_bounds__(256) k_clean_grid()
{
    int tn  = g_touch_count;
    int gsz = gridDim.x * blockDim.x;
    for (int i = blockIdx.x * blockDim.x + threadIdx.x; i < tn; i += gsz) {
        int cellp = g_touch[i];
        g_grid[cellp] = 0u;
        g_bm[cellp / PZ] = 0ULL;     // idempotent word clear
    }
}

// ---------------- K A2: clear hist ----------------
__global__ void __launch_bounds__(NBIN1) k_clean_hist()
{
    g_hist1[threadIdx.x] = 0;
}

// ---------------- K A3: reset counters ----------------
__global__ void k_reset()
{
    if (threadIdx.x == 0) {
        g_touch_count = 0; g_cand_count = 0; g_peak_count = 0; g_ccount = 0;
    }
}

// ---------------- K1 (4th launch -> ncu): warp-autonomous cp.async GEMM MLP -------
// Each warp owns 32 points and a private 2 x 2 KB double buffer. cp.async waits
// are per-thread; __syncwarp() gives cross-lane visibility. NO __syncthreads in
// the mainloop -> warps free-run.
__global__ void __launch_bounds__(MLPB) k_mlp(
    const float* __restrict__ feats,
    const int*   __restrict__ cb, const int* __restrict__ cx,
    const int*   __restrict__ cy, const int* __restrict__ cz,
    const int*   __restrict__ mask,
    const float* __restrict__ W1, const float* __restrict__ b1,
    const float* __restrict__ W2, const float* __restrict__ b2,
    float* __restrict__ out_score)
{
    __shared__ __align__(16) float4 sFbuf[2][WPB][128];   // 16 KB staging
    __shared__ __align__(16) float  sW1s[FIN * FH];       // 8 KB [k][n]
    __shared__ __align__(16) float  sb1s[FH];
    __shared__ __align__(16) float  sW2s[FH];
    __shared__ float sb2s;

    int t    = threadIdx.x;
    int lane = t & 31;
    int warp = t >> 5;
    int ml   = lane >> 3;          // 0..3: point-group within warp
    int n_grp = lane & 7;          // 0..7: 4-col group
    int sw   = ml;                 // XOR swizzle key

    int blockBase = blockIdx.x * MLPB;
    int pbase     = blockBase + warp * 32;   // this warp's 32 points

    // early independent loads (hidden under mainloop)
    int i = blockBase + t;
    bool valid = (i < NPTS);
    int ic = valid ? i : NPTS - 1;
    int vcb = cb[ic], vcx = cx[ic], vcy = cy[ic], vcz = cz[ic], vmask = mask[ic];

    const float4* F4 = reinterpret_cast<const float4*>(feats);
    unsigned sbase = smem_u32(&sFbuf[0][0][0]);

    // stage chunk c (16 feats = 4 float4/point) of this warp's points into buf
    auto stage = [&](int c, int buf) {
        #pragma unroll
        for (int u = 0; u < 4; u++) {
            int lin = u * 32 + lane;        // 0..127
            int p   = lin >> 2;             // warp-local point 0..31
            int f   = lin & 3;              // float4 slot in chunk
            int gp  = pbase + p; if (gp >= NPTS) gp = NPTS - 1;
            const float4* src = F4 + (size_t)gp * 16 + c * 4 + f;
            unsigned dst = sbase +
                (unsigned)(((buf * WPB + warp) * 128) + p * 4 + (f ^ ((p >> 3) & 3))) * 16u;
            CP_ASYNC16(dst, src);
        }
        CP_COMMIT();
    };

    // prefetch chunks 0,1 (groups 0,1)
    stage(0, 0);
    stage(1, 1);

    // weights (block-cooperative; ONE block barrier total)
    for (int k = t; k < FIN * FH; k += MLPB) sW1s[k] = W1[k];
    if (t < FH) { sb1s[t] = b1[t]; sW2s[t] = W2[t]; }
    if (t == 0) sb2s = b2[0];
    __syncthreads();

    unsigned long long acc[16];
    {
        ulonglong2 binit = *reinterpret_cast<const ulonglong2*>(&sb1s[n_grp * 4]);
        #pragma unroll
        for (int pp = 0; pp < 8; pp++) { acc[2 * pp] = binit.x; acc[2 * pp + 1] = binit.y; }
    }

    #pragma unroll
    for (int c = 0; c < 4; c++) {
        int buf = c & 1;
        if (c >= 1 && c + 1 < 4) stage(c + 1, (c + 1) & 1);  // refill buf consumed last iter
        if (c < 3) CP_WAIT1(); else CP_WAIT0();              // own group c complete
        __syncwarp();                                        // => all lanes' group c complete
        #pragma unroll
        for (int j = 0; j < 4; j++) {
            int f0 = c * 16 + j * 4;
            ulonglong2 w0 = *reinterpret_cast<const ulonglong2*>(&sW1s[(f0 + 0) * FH + n_grp * 4]);
            ulonglong2 w1 = *reinterpret_cast<const ulonglong2*>(&sW1s[(f0 + 1) * FH + n_grp * 4]);
            ulonglong2 w2 = *reinterpret_cast<const ulonglong2*>(&sW1s[(f0 + 2) * FH + n_grp * 4]);
            ulonglong2 w3 = *reinterpret_cast<const ulonglong2*>(&sW1s[(f0 + 3) * FH + n_grp * 4]);
            #pragma unroll
            for (int pp = 0; pp < 8; pp++) {
                float4 fv = sFbuf[buf][warp][(ml * 8 + pp) * 4 + (j ^ sw)];
                unsigned long long fp;
                fp = pk2(fv.x); fma2(acc[2*pp], fp, w0.x); fma2(acc[2*pp+1], fp, w0.y);
                fp = pk2(fv.y); fma2(acc[2*pp], fp, w1.x); fma2(acc[2*pp+1], fp, w1.y);
                fp = pk2(fv.z); fma2(acc[2*pp], fp, w2.x); fma2(acc[2*pp+1], fp, w2.y);
                fp = pk2(fv.w); fma2(acc[2*pp], fp, w3.x); fma2(acc[2*pp+1], fp, w3.y);
            }
        }
        __syncwarp();   // warp done with buf before its own refill next iteration
    }

    // ---- second layer: per-thread partial over its 4 cols, butterfly over n_grp ----
    float4 w2v = *reinterpret_cast<const float4*>(&sW2s[n_grp * 4]);
    float part[8];
    #pragma unroll
    for (int pp = 0; pp < 8; pp++) {
        float2 a0 = up2(acc[2 * pp]);
        float2 a1 = up2(acc[2 * pp + 1]);
        float p0 = fmaxf(a0.x, 0.0f) * w2v.x;
        p0 = fmaf(fmaxf(a0.y, 0.0f), w2v.y, p0);
        p0 = fmaf(fmaxf(a1.x, 0.0f), w2v.z, p0);
        p0 = fmaf(fmaxf(a1.y, 0.0f), w2v.w, p0);
        part[pp] = p0;
    }
    #pragma unroll
    for (int off = 1; off < 8; off <<= 1) {
        #pragma unroll
        for (int pp = 0; pp < 8; pp++)
            part[pp] += __shfl_xor_sync(0xFFFFFFFFu, part[pp], off);
    }
    // thread's point = pbase + ml*8 + n_grp = blockBase + t
    float z = part[n_grp] + sb2s;

    // ---- epilogue ----
    float s = 0.0f;
    int cellp = 0;
    unsigned sb = 0u;
    if (valid) {
        s = 1.0f / (1.0f + expf(-z));
        if (vmask == 0) s = 0.0f;
        out_score[i] = s;
        g_cell[i] = (vcb << 24) | (vcx << 15) | (vcy << 6) | vcz;
        cellp = ((vcb * PX + vcx + 1) * PY + vcy + 1) * PZ + (vcz + 1);
        sb = __float_as_uint(s);
    }

    bool dep = valid && (s > SCORE_T);
    if (dep) {
        atomicMax(&g_grid[cellp], sb);
        atomicOr(&g_bm[cellp / PZ], 1ULL << vcz);
    }
    unsigned m = __ballot_sync(0xFFFFFFFFu, dep);
    int base = 0;
    if (lane == 0 && m) base = atomicAdd(&g_touch_count, __popc(m));
    base = __shfl_sync(0xFFFFFFFFu, base, 0);
    if (dep) g_touch[base + __popc(m & ((1u << lane) - 1u))] = cellp;

    bool cnd = valid && (s > CENT_T);
    unsigned m2 = __ballot_sync(0xFFFFFFFFu, cnd);
    int base2 = 0;
    if (lane == 0 && m2) base2 = atomicAdd(&g_cand_count, __popc(m2));
    base2 = __shfl_sync(0xFFFFFFFFu, base2, 0);
    if (cnd) {
        int pos = base2 + __popc(m2 & ((1u << lane) - 1u));
        g_cand[pos]   = ((unsigned long long)sb << 32) | (unsigned)(~(unsigned)i);
        g_ccellp[pos] = cellp;
    }
}

// ---------------- K2: peak detect — batched bitmap loads, then bit probes ---------
__global__ void __launch_bounds__(256) k_peak()
{
    int n   = g_cand_count;
    int gsz = gridDim.x * blockDim.x;
    int idx = blockIdx.x * blockDim.x + threadIdx.x;
    int iters = (n + gsz - 1) / gsz;
    int lane = threadIdx.x & 31;

    for (int it = 0; it < iters; it++, idx += gsz) {
        bool valid = (idx < n);
        unsigned long long key = 0ULL;
        unsigned sb = 0u, hmax = 0u;
        if (valid) {
            key = g_cand[idx];
            sb  = (unsigned)(key >> 32);
            int cp    = g_ccellp[idx];
            int word0 = cp / PZ;
            int zc    = cp - word0 * PZ - 1;     // original z, 0..63
            unsigned long long zmask = (zc == 0) ? 3ULL : (7ULL << (zc - 1));

            // batch all 9 bitmap loads (independent; one L2 round-trip)
            unsigned long long bw[9];
            int wd[9];
            #pragma unroll
            for (int dx = 0; dx < 3; dx++)
                #pragma unroll
                for (int dy = 0; dy < 3; dy++) {
                    int w = word0 + (dx - 1) * PY + (dy - 1);
                    wd[dx * 3 + dy] = w;
                    bw[dx * 3 + dy] = g_bm[w];
                }
            #pragma unroll
            for (int q = 0; q < 9; q++) {
                unsigned long long bits = bw[q] & zmask;
                while (bits) {
                    int j = __ffsll(bits) - 1;
                    bits &= bits - 1;
                    unsigned v = g_grid[wd[q] * PZ + j + 1];
                    hmax = v > hmax ? v : hmax;
                }
            }
        }
        bool isPeak = valid && (hmax == sb);
        unsigned m = __ballot_sync(0xFFFFFFFFu, isPeak);
        int base = 0;
        if (lane == 0 && m) base = atomicAdd(&g_peak_count, __popc(m));
        base = __shfl_sync(0xFFFFFFFFu, base, 0);
        if (isPeak) {
            g_keys[base + __popc(m & ((1u << lane) - 1u))] = key;
            atomicAdd(&g_hist1[(sb >> 16) - BIN1_BASE], 1);
        }
    }
}

// ---------------- K3: single-level threshold (1 block, 512 thr) ----------------
__global__ void __launch_bounds__(NBIN1) k_thresh()
{
    __shared__ int csum[NBIN1];
    int t = threadIdx.x;
    int h = g_hist1[t];
    csum[t] = h;
    __syncthreads();
    for (int off = 1; off < NBIN1; off <<= 1) {
        int v = (t >= off) ? csum[t - off] : 0;
        __syncthreads();
        csum[t] += v;
        __syncthreads();
    }
    int total = csum[NBIN1 - 1];
    if (total < MAXP) {
        if (t == 0) g_thresh = 0u;      // take all peaks
        return;
    }
    int above = total - csum[t];        // strictly above bin t
    if (above < MAXP && above + h >= MAXP)
        g_thresh = ((unsigned)(t + BIN1_BASE)) << 16;
}

// ---------------- K4: compact survivors (grid-wide) ----------------
__global__ void __launch_bounds__(256) k_compact()
{
    int n = g_peak_count;
    unsigned th = g_thresh;
    int gsz = gridDim.x * blockDim.x;
    int idx = blockIdx.x * blockDim.x + threadIdx.x;
    int iters = (n + gsz - 1) / gsz;
    int lane = threadIdx.x & 31;
    for (int it = 0; it < iters; it++, idx += gsz) {
        bool take = false;
        unsigned long long key = 0ULL;
        if (idx < n) {
            key = g_keys[idx];
            take = ((unsigned)(key >> 32) >= th);
        }
        unsigned m = __ballot_sync(0xFFFFFFFFu, take);
        int base = 0;
        if (lane == 0 && m) base = atomicAdd(&g_ccount, __popc(m));
        base = __shfl_sync(0xFFFFFFFFu, base, 0);
        if (take) {
            int pos = base + __popc(m & ((1u << lane) - 1u));
            if (pos < CCAP) g_ckeys[pos] = key;
        }
    }
}

// ---------------- K5: sort 2048 + emit outputs (1 block, 1024 thr) ----------------
__global__ void __launch_bounds__(1024) k_sortout(float* __restrict__ out)
{
    __shared__ unsigned long long sk[CCAP];     // 16 KB
    __shared__ int fill[MAXP];
    __shared__ int sValid;
    int t = threadIdx.x;
    int M = g_ccount; if (M > CCAP) M = CCAP;
    sk[t]        = (t        < M) ? g_ckeys[t]        : 0ULL;
    sk[t + 1024] = (t + 1024 < M) ? g_ckeys[t + 1024] : 0ULL;
    __syncthreads();

    // bitonic sort, descending (2048 elems, 2/thread)
    for (int kk = 2; kk <= CCAP; kk <<= 1) {
        for (int j = kk >> 1; j > 0; j >>= 1) {
            #pragma unroll
            for (int half = 0; half < 2; half++) {
                int i = t + half * 1024;
                int ixj = i ^ j;
                if (ixj > i) {
                    unsigned long long a = sk[i], b = sk[ixj];
                    bool desc = ((i & kk) == 0);
                    if (desc ? (a < b) : (a > b)) { sk[i] = b; sk[ixj] = a; }
                }
            }
            __syncthreads();
        }
    }

    if (t == 0) {
        int valid = M < MAXP ? M : MAXP;
        sValid = valid;
        if (valid < MAXP) {   // practically never taken
            int need = MAXP - valid, got = 0;
            for (int i = 0; i < NPTS && got < need; i++) {
                bool isP = false;
                for (int q = 0; q < valid; q++) {
                    int pidx = (int)(~(unsigned)(sk[q] & 0xFFFFFFFFu));
                    if (pidx == i) { isP = true; break; }
                }
                if (!isP) { fill[valid + got] = i; got++; }
            }
        }
    }
    __syncthreads();

    if (t < MAXP) {
        int valid = sValid;
        float sc; int idx;
        if (t < valid) {
            unsigned long long key = sk[t];
            sc  = __uint_as_float((unsigned)(key >> 32));
            idx = (int)(~(unsigned)(key & 0xFFFFFFFFu));
        } else {
            sc  = -1.0f;
            idx = fill[t];
        }
        out[NPTS + t]        = (float)idx;
        out[NPTS + MAXP + t] = sc;
        int cell = g_cell[idx];
        float* pc = out + NPTS + 2 * MAXP + (size_t)t * 4;
        pc[0] = (float)(cell >> 24);
        pc[1] = (float)((cell >> 15) & 511);
        pc[2] = (float)((cell >> 6) & 511);
        pc[3] = (float)(cell & 63);
    }
}

// ---------------- launch ----------------
extern "C" void kernel_launch(void* const* d_in, const int* in_sizes, int n_in,
                              void* d_out, int out_size) {
    const float* feats = (const float*)d_in[0];
    const int*   cb    = (const int*)  d_in[1];
    const int*   cx    = (const int*)  d_in[2];
    const int*   cy    = (const int*)  d_in[3];
    const int*   cz    = (const int*)  d_in[4];
    const int*   mask  = (const int*)  d_in[5];
    const float* W1    = (const float*)d_in[6];
    const float* b1    = (const float*)d_in[7];
    const float* W2    = (const float*)d_in[8];
    const float* b2    = (const float*)d_in[9];
    float* out = (float*)d_out;

    // cleanup of PREVIOUS replay's state runs first; no-op on the very first call.
    k_clean_grid<<<2048, 256>>>();
    k_clean_hist<<<1, NBIN1>>>();
    k_reset<<<1, 32>>>();
    k_mlp<<<(NPTS + MLPB - 1) / MLPB, MLPB>>>(feats, cb, cx, cy, cz, mask,
                                              W1, b1, W2, b2, out);   // 4th launch -> ncu
    k_peak<<<2048, 256>>>();
    k_thresh<<<1, NBIN1>>>();
    k_compact<<<512, 256>>>();
    k_sortout<<<1, 1024>>>(out);
}